// round 15
// baseline (speedup 1.0000x reference)
#include <cuda_runtime.h>
#include <cuda_fp16.h>
#include <cstdint>
#include <cstddef>

// Problem constants
#define BHD   64            // B*H
#define SEQ   2048
#define DH    64
#define QT    128           // Q rows per CTA
#define BC    64            // K/V rows per iteration
#define NIT   (SEQ / BC)    // 32
#define ELEMS (BHD * SEQ * DH)
#define PAD   72            // halves per smem row (16B-aligned, conflict-free)
#define ROWB  (PAD * 2)     // 144 bytes

// fp16 scratch (device globals — allocation-free)
__device__ __align__(16) __half g_q[ELEMS];   // Q pre-scaled by 0.125*log2(e)
__device__ __align__(16) __half g_k[ELEMS];
__device__ __align__(16) __half g_v[ELEMS];

// ---------------- low-level helpers ----------------
__device__ __forceinline__ uint32_t smem_u32(const void* p) {
    uint32_t a;
    asm("{ .reg .u64 t; cvta.to.shared.u64 t, %1; cvt.u32.u64 %0, t; }" : "=r"(a) : "l"(p));
    return a;
}
__device__ __forceinline__ void cp16(uint32_t dst, const void* src) {
    asm volatile("cp.async.cg.shared.global [%0], [%1], 16;" :: "r"(dst), "l"(src));
}
#define CP_COMMIT() asm volatile("cp.async.commit_group;" ::: "memory")
#define CP_WAIT(n)  asm volatile("cp.async.wait_group %0;" :: "n"(n) : "memory")

__device__ __forceinline__ void ldsm4(uint32_t& r0, uint32_t& r1, uint32_t& r2, uint32_t& r3, uint32_t a) {
    asm volatile("ldmatrix.sync.aligned.m8n8.x4.shared.b16 {%0,%1,%2,%3}, [%4];"
                 : "=r"(r0), "=r"(r1), "=r"(r2), "=r"(r3) : "r"(a));
}
__device__ __forceinline__ void ldsm4t(uint32_t& r0, uint32_t& r1, uint32_t& r2, uint32_t& r3, uint32_t a) {
    asm volatile("ldmatrix.sync.aligned.m8n8.x4.trans.shared.b16 {%0,%1,%2,%3}, [%4];"
                 : "=r"(r0), "=r"(r1), "=r"(r2), "=r"(r3) : "r"(a));
}
// D += A * B  (m16n8k16, f16 in, f32 accum); D aliases C.
__device__ __forceinline__ void mma16816(float& d0, float& d1, float& d2, float& d3,
                                         uint32_t a0, uint32_t a1, uint32_t a2, uint32_t a3,
                                         uint32_t b0, uint32_t b1) {
    asm volatile("mma.sync.aligned.m16n8k16.row.col.f32.f16.f16.f32 "
                 "{%0,%1,%2,%3}, {%4,%5,%6,%7}, {%8,%9}, {%0,%1,%2,%3};"
                 : "+f"(d0), "+f"(d1), "+f"(d2), "+f"(d3)
                 : "r"(a0), "r"(a1), "r"(a2), "r"(a3), "r"(b0), "r"(b1));
}
__device__ __forceinline__ float ex2(float x) {
    float y;
    asm("ex2.approx.f32 %0, %1;" : "=f"(y) : "f"(x));
    return y;
}
__device__ __forceinline__ uint32_t pack_h2(float a, float b) {
    __half2 h = __floats2half2_rn(a, b);
    return *reinterpret_cast<uint32_t*>(&h);
}

// ---------------- pre-pass converts ----------------
__global__ void cvt_q_kernel(const float4* __restrict__ s) {
    const float c = 0.125f * 1.4426950408889634f;   // 1/sqrt(64) * log2(e)
    int i = blockIdx.x * 256 + threadIdx.x;
    float4 f = s[i];
    uint2 u;
    u.x = pack_h2(f.x * c, f.y * c);
    u.y = pack_h2(f.z * c, f.w * c);
    reinterpret_cast<uint2*>(g_q)[i] = u;
}
__global__ void cvt_k_kernel(const float4* __restrict__ s) {
    int i = blockIdx.x * 256 + threadIdx.x;
    float4 f = s[i];
    uint2 u;
    u.x = pack_h2(f.x, f.y);
    u.y = pack_h2(f.z, f.w);
    reinterpret_cast<uint2*>(g_k)[i] = u;
}
__global__ void cvt_v_kernel(const float4* __restrict__ s) {
    int i = blockIdx.x * 256 + threadIdx.x;
    float4 f = s[i];
    uint2 u;
    u.x = pack_h2(f.x, f.y);
    u.y = pack_h2(f.z, f.w);
    reinterpret_cast<uint2*>(g_v)[i] = u;
}

// ---------------- tile loader: 64 rows x 64 halves -> padded smem ----------------
__device__ __forceinline__ void load_tile(uint32_t dstb, const __half* src, int tid) {
    #pragma unroll
    for (int i = 0; i < 4; i++) {
        int c = tid + i * 128;           // 512 chunks of 16B
        int r = c >> 3, cg = c & 7;
        cp16(dstb + r * ROWB + cg * 16, src + r * DH + cg * 8);
    }
}

// ---------------- flash-attention main kernel (mma.sync / HMMA) ----------------
__global__ __launch_bounds__(128, 2) void fa_kernel(float* __restrict__ out) {
    __shared__ __align__(16) __half sm[4 * BC * PAD];   // K0,K1,V0,V1 (Q staged over K0+K1)
    const int tid = threadIdx.x;
    const int wid = tid >> 5;
    const int lid = tid & 31;
    const int g4  = lid >> 2;     // row group within 8
    const int t4  = lid & 3;      // col pair id
    const int bh  = blockIdx.y;
    const int qt  = blockIdx.x;

    const uint32_t sb = smem_u32(sm);
    const uint32_t Kb0 = sb;
    const uint32_t Kb1 = sb + BC * ROWB;
    const uint32_t Vb0 = sb + 2 * BC * ROWB;
    const uint32_t Vb1 = sb + 3 * BC * ROWB;

    const __half* Qg = g_q + ((size_t)bh * SEQ + (size_t)qt * QT) * DH;
    const __half* Kg = g_k + (size_t)bh * SEQ * DH;
    const __half* Vg = g_v + (size_t)bh * SEQ * DH;

    // ---- stage Q (128x64) into [Kb0..Kb1] region, then load A-fragments ----
    #pragma unroll
    for (int i = 0; i < 8; i++) {
        int c = tid + i * 128;           // 1024 chunks
        int r = c >> 3, cg = c & 7;
        cp16(sb + r * ROWB + cg * 16, Qg + r * DH + cg * 8);
    }
    CP_COMMIT();
    CP_WAIT(0);
    __syncthreads();

    uint32_t qa[2][4][4];
    {
        const int m0 = wid * 32;
        const uint32_t base = sb + (m0 + (lid & 15)) * ROWB + (lid >> 4) * 16;
        #pragma unroll
        for (int mt = 0; mt < 2; mt++)
            #pragma unroll
            for (int kt = 0; kt < 4; kt++)
                ldsm4(qa[mt][kt][0], qa[mt][kt][1], qa[mt][kt][2], qa[mt][kt][3],
                      base + mt * 16 * ROWB + kt * 32);
    }
    __syncthreads();

    // ---- pipeline prologue: tiles 0 and 1 ----
    load_tile(Kb0, Kg, tid);
    load_tile(Vb0, Vg, tid);
    CP_COMMIT();
    load_tile(Kb1, Kg + BC * DH, tid);
    load_tile(Vb1, Vg + BC * DH, tid);
    CP_COMMIT();

    // per-lane ldmatrix address components
    const uint32_t k_off = ((lid & 7) + ((lid >> 4) << 3)) * ROWB + (((lid >> 3) & 1) << 4);
    const uint32_t v_off = (lid & 15) * ROWB + ((lid >> 4) << 4);

    // accumulators
    float o[2][8][4];
    #pragma unroll
    for (int mt = 0; mt < 2; mt++)
        #pragma unroll
        for (int dt = 0; dt < 8; dt++)
            #pragma unroll
            for (int r = 0; r < 4; r++) o[mt][dt][r] = 0.f;
    float mrow[2][2] = {{-1e30f, -1e30f}, {-1e30f, -1e30f}};
    float lrow[2][2] = {{0.f, 0.f}, {0.f, 0.f}};

    for (int it = 0; it < NIT; ++it) {
        CP_WAIT(1);
        __syncthreads();
        const uint32_t Kbuf = (it & 1) ? Kb1 : Kb0;
        const uint32_t Vbuf = (it & 1) ? Vb1 : Vb0;

        // ---- S = Q * K^T  (2m x 8n x 4k HMMA) ----
        float s[2][8][4];
        #pragma unroll
        for (int mt = 0; mt < 2; mt++)
            #pragma unroll
            for (int nt = 0; nt < 8; nt++)
                #pragma unroll
                for (int r = 0; r < 4; r++) s[mt][nt][r] = 0.f;

        #pragma unroll
        for (int kt = 0; kt < 4; kt++) {
            #pragma unroll
            for (int np = 0; np < 4; np++) {
                uint32_t b0, b1, b2, b3;
                ldsm4(b0, b1, b2, b3, Kbuf + k_off + np * 16 * ROWB + kt * 32);
                #pragma unroll
                for (int mt = 0; mt < 2; mt++) {
                    mma16816(s[mt][2*np][0], s[mt][2*np][1], s[mt][2*np][2], s[mt][2*np][3],
                             qa[mt][kt][0], qa[mt][kt][1], qa[mt][kt][2], qa[mt][kt][3], b0, b1);
                    mma16816(s[mt][2*np+1][0], s[mt][2*np+1][1], s[mt][2*np+1][2], s[mt][2*np+1][3],
                             qa[mt][kt][0], qa[mt][kt][1], qa[mt][kt][2], qa[mt][kt][3], b2, b3);
                }
            }
        }

        // ---- online softmax (S already in log2-scaled domain) ----
        float mn[2][2], alpha[2][2];
        #pragma unroll
        for (int mt = 0; mt < 2; mt++) {
            float a0 = mrow[mt][0], a1 = mrow[mt][1];
            #pragma unroll
            for (int nt = 0; nt < 8; nt++) {
                a0 = fmaxf(a0, fmaxf(s[mt][nt][0], s[mt][nt][1]));
                a1 = fmaxf(a1, fmaxf(s[mt][nt][2], s[mt][nt][3]));
            }
            a0 = fmaxf(a0, __shfl_xor_sync(0xffffffffu, a0, 1));
            a0 = fmaxf(a0, __shfl_xor_sync(0xffffffffu, a0, 2));
            a1 = fmaxf(a1, __shfl_xor_sync(0xffffffffu, a1, 1));
            a1 = fmaxf(a1, __shfl_xor_sync(0xffffffffu, a1, 2));
            mn[mt][0] = a0; mn[mt][1] = a1;
            alpha[mt][0] = ex2(mrow[mt][0] - a0);
            alpha[mt][1] = ex2(mrow[mt][1] - a1);
            mrow[mt][0] = a0; mrow[mt][1] = a1;
        }

        // ---- exponentiate, pack P A-fragments, partial row sums ----
        uint32_t pa[2][4][4];
        #pragma unroll
        for (int mt = 0; mt < 2; mt++) {
            float ls0 = 0.f, ls1 = 0.f;
            #pragma unroll
            for (int nt = 0; nt < 8; nt++) {
                float p0 = ex2(s[mt][nt][0] - mn[mt][0]);
                float p1 = ex2(s[mt][nt][1] - mn[mt][0]);
                float p2 = ex2(s[mt][nt][2] - mn[mt][1]);
                float p3 = ex2(s[mt][nt][3] - mn[mt][1]);
                ls0 += p0 + p1;
                ls1 += p2 + p3;
                const int kt = nt >> 1;
                if ((nt & 1) == 0) {
                    pa[mt][kt][0] = pack_h2(p0, p1);
                    pa[mt][kt][1] = pack_h2(p2, p3);
                } else {
                    pa[mt][kt][2] = pack_h2(p0, p1);
                    pa[mt][kt][3] = pack_h2(p2, p3);
                }
            }
            lrow[mt][0] = lrow[mt][0] * alpha[mt][0] + ls0;
            lrow[mt][1] = lrow[mt][1] * alpha[mt][1] + ls1;
        }

        // ---- rescale O by alpha ----
        #pragma unroll
        for (int mt = 0; mt < 2; mt++)
            #pragma unroll
            for (int dt = 0; dt < 8; dt++) {
                o[mt][dt][0] *= alpha[mt][0];
                o[mt][dt][1] *= alpha[mt][0];
                o[mt][dt][2] *= alpha[mt][1];
                o[mt][dt][3] *= alpha[mt][1];
            }

        // ---- O += P * V  (2m x 8n x 4k HMMA, V via ldmatrix.trans) ----
        #pragma unroll
        for (int kt = 0; kt < 4; kt++) {
            #pragma unroll
            for (int dp = 0; dp < 4; dp++) {
                uint32_t b0, b1, b2, b3;
                ldsm4t(b0, b1, b2, b3, Vbuf + v_off + kt * 16 * ROWB + dp * 32);
                #pragma unroll
                for (int mt = 0; mt < 2; mt++) {
                    mma16816(o[mt][2*dp][0], o[mt][2*dp][1], o[mt][2*dp][2], o[mt][2*dp][3],
                             pa[mt][kt][0], pa[mt][kt][1], pa[mt][kt][2], pa[mt][kt][3], b0, b1);
                    mma16816(o[mt][2*dp+1][0], o[mt][2*dp+1][1], o[mt][2*dp+1][2], o[mt][2*dp+1][3],
                             pa[mt][kt][0], pa[mt][kt][1], pa[mt][kt][2], pa[mt][kt][3], b2, b3);
                }
            }
        }

        // ---- refill the just-consumed buffer with tile it+2 ----
        __syncthreads();
        if (it + 2 < NIT) {
            load_tile(Kbuf, Kg + (size_t)(it + 2) * BC * DH, tid);
            load_tile(Vbuf, Vg + (size_t)(it + 2) * BC * DH, tid);
        }
        CP_COMMIT();   // always commit: keeps group accounting uniform
    }

    // ---- epilogue: finish l over the quad, normalize, store fp32 ----
    float inv[2][2];
    #pragma unroll
    for (int mt = 0; mt < 2; mt++)
        #pragma unroll
        for (int h = 0; h < 2; h++) {
            float l = lrow[mt][h];
            l += __shfl_xor_sync(0xffffffffu, l, 1);
            l += __shfl_xor_sync(0xffffffffu, l, 2);
            inv[mt][h] = 1.0f / l;
        }

    float* ob = out + ((size_t)bh * SEQ + (size_t)qt * QT) * DH;
    const int m0 = wid * 32;
    #pragma unroll
    for (int mt = 0; mt < 2; mt++) {
        const int r0 = m0 + mt * 16 + g4;
        #pragma unroll
        for (int dt = 0; dt < 8; dt++) {
            const int col = dt * 8 + t4 * 2;
            float2 w0 = { o[mt][dt][0] * inv[mt][0], o[mt][dt][1] * inv[mt][0] };
            float2 w1 = { o[mt][dt][2] * inv[mt][1], o[mt][dt][3] * inv[mt][1] };
            *reinterpret_cast<float2*>(ob + (size_t)r0 * DH + col)       = w0;
            *reinterpret_cast<float2*>(ob + (size_t)(r0 + 8) * DH + col) = w1;
        }
    }
}

// ---------------- launch ----------------
extern "C" void kernel_launch(void* const* d_in, const int* in_sizes, int n_in,
                              void* d_out, int out_size) {
    const float* q = (const float*)d_in[0];
    const float* k = (const float*)d_in[1];
    const float* v = (const float*)d_in[2];
    float* out = (float*)d_out;

    // fp32 -> fp16 converts (Q pre-scaled by 1/sqrt(D)*log2e)
    cvt_q_kernel<<<ELEMS / 1024, 256>>>((const float4*)q);
    cvt_k_kernel<<<ELEMS / 1024, 256>>>((const float4*)k);
    cvt_v_kernel<<<ELEMS / 1024, 256>>>((const float4*)v);

    // flash attention: 16 q-tiles (fastest -> same-head CTAs co-scheduled) x 64 heads
    fa_kernel<<<dim3(SEQ / QT, BHD), 128>>>(out);
}

// round 16
// speedup vs baseline: 1.0018x; 1.0018x over previous
#include <cuda_runtime.h>
#include <cuda_fp16.h>
#include <cstdint>
#include <cstddef>

// Problem constants
#define BHD   64            // B*H
#define SEQ   2048
#define DH    64
#define QT    128           // Q rows per CTA
#define BC    64            // K/V rows per iteration
#define NIT   (SEQ / BC)    // 32
#define ELEMS (BHD * SEQ * DH)
#define PAD   72            // halves per smem row (16B-aligned, conflict-free)
#define ROWB  (PAD * 2)     // 144 bytes

// fp16 scratch (device globals — allocation-free)
__device__ __align__(16) __half g_q[ELEMS];   // Q pre-scaled by 0.125*log2(e)
__device__ __align__(16) __half g_k[ELEMS];
__device__ __align__(16) __half g_v[ELEMS];

// ---------------- low-level helpers ----------------
__device__ __forceinline__ uint32_t smem_u32(const void* p) {
    uint32_t a;
    asm("{ .reg .u64 t; cvta.to.shared.u64 t, %1; cvt.u32.u64 %0, t; }" : "=r"(a) : "l"(p));
    return a;
}
__device__ __forceinline__ void cp16(uint32_t dst, const void* src) {
    asm volatile("cp.async.cg.shared.global [%0], [%1], 16;" :: "r"(dst), "l"(src));
}
#define CP_COMMIT() asm volatile("cp.async.commit_group;" ::: "memory")
#define CP_WAIT(n)  asm volatile("cp.async.wait_group %0;" :: "n"(n) : "memory")

__device__ __forceinline__ void ldsm4(uint32_t& r0, uint32_t& r1, uint32_t& r2, uint32_t& r3, uint32_t a) {
    asm volatile("ldmatrix.sync.aligned.m8n8.x4.shared.b16 {%0,%1,%2,%3}, [%4];"
                 : "=r"(r0), "=r"(r1), "=r"(r2), "=r"(r3) : "r"(a));
}
__device__ __forceinline__ void ldsm4t(uint32_t& r0, uint32_t& r1, uint32_t& r2, uint32_t& r3, uint32_t a) {
    asm volatile("ldmatrix.sync.aligned.m8n8.x4.trans.shared.b16 {%0,%1,%2,%3}, [%4];"
                 : "=r"(r0), "=r"(r1), "=r"(r2), "=r"(r3) : "r"(a));
}
// D += A * B  (m16n8k16, f16 in, f32 accum); D aliases C.
__device__ __forceinline__ void mma16816(float& d0, float& d1, float& d2, float& d3,
                                         uint32_t a0, uint32_t a1, uint32_t a2, uint32_t a3,
                                         uint32_t b0, uint32_t b1) {
    asm volatile("mma.sync.aligned.m16n8k16.row.col.f32.f16.f16.f32 "
                 "{%0,%1,%2,%3}, {%4,%5,%6,%7}, {%8,%9}, {%0,%1,%2,%3};"
                 : "+f"(d0), "+f"(d1), "+f"(d2), "+f"(d3)
                 : "r"(a0), "r"(a1), "r"(a2), "r"(a3), "r"(b0), "r"(b1));
}
__device__ __forceinline__ float ex2(float x) {
    float y;
    asm("ex2.approx.f32 %0, %1;" : "=f"(y) : "f"(x));
    return y;
}
__device__ __forceinline__ uint32_t pack_h2(float a, float b) {
    __half2 h = __floats2half2_rn(a, b);
    return *reinterpret_cast<uint32_t*>(&h);
}

// ---------------- pre-pass converts ----------------
__global__ void cvt_q_kernel(const float4* __restrict__ s) {
    const float c = 0.125f * 1.4426950408889634f;   // 1/sqrt(64) * log2(e)
    int i = blockIdx.x * 256 + threadIdx.x;
    float4 f = s[i];
    uint2 u;
    u.x = pack_h2(f.x * c, f.y * c);
    u.y = pack_h2(f.z * c, f.w * c);
    reinterpret_cast<uint2*>(g_q)[i] = u;
}
__global__ void cvt_k_kernel(const float4* __restrict__ s) {
    int i = blockIdx.x * 256 + threadIdx.x;
    float4 f = s[i];
    uint2 u;
    u.x = pack_h2(f.x, f.y);
    u.y = pack_h2(f.z, f.w);
    reinterpret_cast<uint2*>(g_k)[i] = u;
}
__global__ void cvt_v_kernel(const float4* __restrict__ s) {
    int i = blockIdx.x * 256 + threadIdx.x;
    float4 f = s[i];
    uint2 u;
    u.x = pack_h2(f.x, f.y);
    u.y = pack_h2(f.z, f.w);
    reinterpret_cast<uint2*>(g_v)[i] = u;
}

// ---------------- tile loader: 64 rows x 64 halves -> padded smem ----------------
__device__ __forceinline__ void load_tile(uint32_t dstb, const __half* src, int tid) {
    #pragma unroll
    for (int i = 0; i < 4; i++) {
        int c = tid + i * 128;           // 512 chunks of 16B
        int r = c >> 3, cg = c & 7;
        cp16(dstb + r * ROWB + cg * 16, src + r * DH + cg * 8);
    }
}

// ---------------- flash-attention main kernel (mma.sync / HMMA) ----------------
__global__ __launch_bounds__(128, 2) void fa_kernel(float* __restrict__ out) {
    __shared__ __align__(16) __half sm[4 * BC * PAD];   // K0,K1,V0,V1 (Q staged over K0+K1)
    const int tid = threadIdx.x;
    const int wid = tid >> 5;
    const int lid = tid & 31;
    const int g4  = lid >> 2;     // row group within 8
    const int t4  = lid & 3;      // col pair id
    const int bh  = blockIdx.y;
    const int qt  = blockIdx.x;

    const uint32_t sb = smem_u32(sm);
    const uint32_t Kb0 = sb;
    const uint32_t Kb1 = sb + BC * ROWB;
    const uint32_t Vb0 = sb + 2 * BC * ROWB;
    const uint32_t Vb1 = sb + 3 * BC * ROWB;

    const __half* Qg = g_q + ((size_t)bh * SEQ + (size_t)qt * QT) * DH;
    const __half* Kg = g_k + (size_t)bh * SEQ * DH;
    const __half* Vg = g_v + (size_t)bh * SEQ * DH;

    // ---- stage Q (128x64) into [Kb0..Kb1] region, then load A-fragments ----
    #pragma unroll
    for (int i = 0; i < 8; i++) {
        int c = tid + i * 128;           // 1024 chunks
        int r = c >> 3, cg = c & 7;
        cp16(sb + r * ROWB + cg * 16, Qg + r * DH + cg * 8);
    }
    CP_COMMIT();
    CP_WAIT(0);
    __syncthreads();

    uint32_t qa[2][4][4];
    {
        const int m0 = wid * 32;
        const uint32_t base = sb + (m0 + (lid & 15)) * ROWB + (lid >> 4) * 16;
        #pragma unroll
        for (int mt = 0; mt < 2; mt++)
            #pragma unroll
            for (int kt = 0; kt < 4; kt++)
                ldsm4(qa[mt][kt][0], qa[mt][kt][1], qa[mt][kt][2], qa[mt][kt][3],
                      base + mt * 16 * ROWB + kt * 32);
    }
    __syncthreads();

    // ---- pipeline prologue: tiles 0 and 1 ----
    load_tile(Kb0, Kg, tid);
    load_tile(Vb0, Vg, tid);
    CP_COMMIT();
    load_tile(Kb1, Kg + BC * DH, tid);
    load_tile(Vb1, Vg + BC * DH, tid);
    CP_COMMIT();

    // per-lane ldmatrix address components
    const uint32_t k_off = ((lid & 7) + ((lid >> 4) << 3)) * ROWB + (((lid >> 3) & 1) << 4);
    const uint32_t v_off = (lid & 15) * ROWB + ((lid >> 4) << 4);

    // accumulators
    float o[2][8][4];
    #pragma unroll
    for (int mt = 0; mt < 2; mt++)
        #pragma unroll
        for (int dt = 0; dt < 8; dt++)
            #pragma unroll
            for (int r = 0; r < 4; r++) o[mt][dt][r] = 0.f;
    float mrow[2][2] = {{-1e30f, -1e30f}, {-1e30f, -1e30f}};
    float lrow[2][2] = {{0.f, 0.f}, {0.f, 0.f}};

    for (int it = 0; it < NIT; ++it) {
        CP_WAIT(1);
        __syncthreads();
        const uint32_t Kbuf = (it & 1) ? Kb1 : Kb0;
        const uint32_t Vbuf = (it & 1) ? Vb1 : Vb0;

        // ---- S = Q * K^T  (2m x 8n x 4k HMMA) ----
        float s[2][8][4];
        #pragma unroll
        for (int mt = 0; mt < 2; mt++)
            #pragma unroll
            for (int nt = 0; nt < 8; nt++)
                #pragma unroll
                for (int r = 0; r < 4; r++) s[mt][nt][r] = 0.f;

        #pragma unroll
        for (int kt = 0; kt < 4; kt++) {
            #pragma unroll
            for (int np = 0; np < 4; np++) {
                uint32_t b0, b1, b2, b3;
                ldsm4(b0, b1, b2, b3, Kbuf + k_off + np * 16 * ROWB + kt * 32);
                #pragma unroll
                for (int mt = 0; mt < 2; mt++) {
                    mma16816(s[mt][2*np][0], s[mt][2*np][1], s[mt][2*np][2], s[mt][2*np][3],
                             qa[mt][kt][0], qa[mt][kt][1], qa[mt][kt][2], qa[mt][kt][3], b0, b1);
                    mma16816(s[mt][2*np+1][0], s[mt][2*np+1][1], s[mt][2*np+1][2], s[mt][2*np+1][3],
                             qa[mt][kt][0], qa[mt][kt][1], qa[mt][kt][2], qa[mt][kt][3], b2, b3);
                }
            }
        }

        // ---- online softmax (S already in log2-scaled domain) ----
        float mn[2][2], alpha[2][2];
        #pragma unroll
        for (int mt = 0; mt < 2; mt++) {
            float a0 = mrow[mt][0], a1 = mrow[mt][1];
            #pragma unroll
            for (int nt = 0; nt < 8; nt++) {
                a0 = fmaxf(a0, fmaxf(s[mt][nt][0], s[mt][nt][1]));
                a1 = fmaxf(a1, fmaxf(s[mt][nt][2], s[mt][nt][3]));
            }
            a0 = fmaxf(a0, __shfl_xor_sync(0xffffffffu, a0, 1));
            a0 = fmaxf(a0, __shfl_xor_sync(0xffffffffu, a0, 2));
            a1 = fmaxf(a1, __shfl_xor_sync(0xffffffffu, a1, 1));
            a1 = fmaxf(a1, __shfl_xor_sync(0xffffffffu, a1, 2));
            mn[mt][0] = a0; mn[mt][1] = a1;
            alpha[mt][0] = ex2(mrow[mt][0] - a0);
            alpha[mt][1] = ex2(mrow[mt][1] - a1);
            mrow[mt][0] = a0; mrow[mt][1] = a1;
        }

        // ---- exponentiate, pack P A-fragments, partial row sums ----
        uint32_t pa[2][4][4];
        #pragma unroll
        for (int mt = 0; mt < 2; mt++) {
            float ls0 = 0.f, ls1 = 0.f;
            #pragma unroll
            for (int nt = 0; nt < 8; nt++) {
                float p0 = ex2(s[mt][nt][0] - mn[mt][0]);
                float p1 = ex2(s[mt][nt][1] - mn[mt][0]);
                float p2 = ex2(s[mt][nt][2] - mn[mt][1]);
                float p3 = ex2(s[mt][nt][3] - mn[mt][1]);
                ls0 += p0 + p1;
                ls1 += p2 + p3;
                const int kt = nt >> 1;
                if ((nt & 1) == 0) {
                    pa[mt][kt][0] = pack_h2(p0, p1);
                    pa[mt][kt][1] = pack_h2(p2, p3);
                } else {
                    pa[mt][kt][2] = pack_h2(p0, p1);
                    pa[mt][kt][3] = pack_h2(p2, p3);
                }
            }
            lrow[mt][0] = lrow[mt][0] * alpha[mt][0] + ls0;
            lrow[mt][1] = lrow[mt][1] * alpha[mt][1] + ls1;
        }

        // ---- rescale O by alpha ----
        #pragma unroll
        for (int mt = 0; mt < 2; mt++)
            #pragma unroll
            for (int dt = 0; dt < 8; dt++) {
                o[mt][dt][0] *= alpha[mt][0];
                o[mt][dt][1] *= alpha[mt][0];
                o[mt][dt][2] *= alpha[mt][1];
                o[mt][dt][3] *= alpha[mt][1];
            }

        // ---- O += P * V  (2m x 8n x 4k HMMA, V via ldmatrix.trans) ----
        #pragma unroll
        for (int kt = 0; kt < 4; kt++) {
            #pragma unroll
            for (int dp = 0; dp < 4; dp++) {
                uint32_t b0, b1, b2, b3;
                ldsm4t(b0, b1, b2, b3, Vbuf + v_off + kt * 16 * ROWB + dp * 32);
                #pragma unroll
                for (int mt = 0; mt < 2; mt++) {
                    mma16816(o[mt][2*dp][0], o[mt][2*dp][1], o[mt][2*dp][2], o[mt][2*dp][3],
                             pa[mt][kt][0], pa[mt][kt][1], pa[mt][kt][2], pa[mt][kt][3], b0, b1);
                    mma16816(o[mt][2*dp+1][0], o[mt][2*dp+1][1], o[mt][2*dp+1][2], o[mt][2*dp+1][3],
                             pa[mt][kt][0], pa[mt][kt][1], pa[mt][kt][2], pa[mt][kt][3], b2, b3);
                }
            }
        }

        // ---- refill the just-consumed buffer with tile it+2 ----
        __syncthreads();
        if (it + 2 < NIT) {
            load_tile(Kbuf, Kg + (size_t)(it + 2) * BC * DH, tid);
            load_tile(Vbuf, Vg + (size_t)(it + 2) * BC * DH, tid);
        }
        CP_COMMIT();   // always commit: keeps group accounting uniform
    }

    // ---- epilogue: finish l over the quad, normalize, store fp32 ----
    float inv[2][2];
    #pragma unroll
    for (int mt = 0; mt < 2; mt++)
        #pragma unroll
        for (int h = 0; h < 2; h++) {
            float l = lrow[mt][h];
            l += __shfl_xor_sync(0xffffffffu, l, 1);
            l += __shfl_xor_sync(0xffffffffu, l, 2);
            inv[mt][h] = 1.0f / l;
        }

    float* ob = out + ((size_t)bh * SEQ + (size_t)qt * QT) * DH;
    const int m0 = wid * 32;
    #pragma unroll
    for (int mt = 0; mt < 2; mt++) {
        const int r0 = m0 + mt * 16 + g4;
        #pragma unroll
        for (int dt = 0; dt < 8; dt++) {
            const int col = dt * 8 + t4 * 2;
            float2 w0 = { o[mt][dt][0] * inv[mt][0], o[mt][dt][1] * inv[mt][0] };
            float2 w1 = { o[mt][dt][2] * inv[mt][1], o[mt][dt][3] * inv[mt][1] };
            *reinterpret_cast<float2*>(ob + (size_t)r0 * DH + col)       = w0;
            *reinterpret_cast<float2*>(ob + (size_t)(r0 + 8) * DH + col) = w1;
        }
    }
}

// ---------------- launch ----------------
extern "C" void kernel_launch(void* const* d_in, const int* in_sizes, int n_in,
                              void* d_out, int out_size) {
    const float* q = (const float*)d_in[0];
    const float* k = (const float*)d_in[1];
    const float* v = (const float*)d_in[2];
    float* out = (float*)d_out;

    // fp32 -> fp16 converts (Q pre-scaled by 1/sqrt(D)*log2e)
    cvt_q_kernel<<<ELEMS / 1024, 256>>>((const float4*)q);
    cvt_k_kernel<<<ELEMS / 1024, 256>>>((const float4*)k);
    cvt_v_kernel<<<ELEMS / 1024, 256>>>((const float4*)v);

    // flash attention: 16 q-tiles (fastest -> same-head CTAs co-scheduled) x 64 heads
    fa_kernel<<<dim3(SEQ / QT, BHD), 128>>>(out);
}